// round 1
// baseline (speedup 1.0000x reference)
#include <cuda_runtime.h>
#include <math.h>

#define NJ 34
#define NV 500000
#define NB 32

// Tree parents (fixed)
__constant__ int c_parents[NJ] = {
    -1, 0, 1, 2, 2, 4, 5, 6, 7, 8, 9, 7, 11, 12, 7, 14, 15, 2,
    17, 18, 19, 20, 21, 22, 20, 24, 25, 20, 27, 28, 0, 30, 0, 32
};

// Scratch (no device alloc allowed): scaled 3x4 affines + (disp+est) table
__device__ float g_A[NJ * 12];     // per joint: row-major 3x4, pre-multiplied by scale
__device__ float g_base[NB * 4];   // per batch: {dx+ex, dy+ey, dz+ez, 0}

// ---------------------------------------------------------------------------
// Kernel 1: rodrigues + forward kinematics + fold scale/displacement/est.
// One block, tiny.
// ---------------------------------------------------------------------------
__global__ void prep_kernel(const float* __restrict__ pose,
                            const float* __restrict__ joints,
                            const float* __restrict__ disp,
                            const float* __restrict__ scale,
                            const float* __restrict__ est)
{
    __shared__ float sR[NJ * 9];
    __shared__ float sJ[NJ * 3];
    __shared__ float sG[NJ * 12];
    int t = threadIdx.x;

    if (t < NJ) {
        float rx = pose[t * 3 + 0], ry = pose[t * 3 + 1], rz = pose[t * 3 + 2];
        float ang = sqrtf(rx * rx + ry * ry + rz * rz + 1e-8f);
        float inv = 1.0f / ang;
        float x = rx * inv, y = ry * inv, z = rz * inv;
        float s = sinf(ang), c = cosf(ang), oc = 1.0f - c;
        float* R = sR + t * 9;
        R[0] = c + oc * x * x;      R[1] = oc * x * y - s * z;  R[2] = oc * x * z + s * y;
        R[3] = oc * x * y + s * z;  R[4] = c + oc * y * y;      R[5] = oc * y * z - s * x;
        R[6] = oc * x * z - s * y;  R[7] = oc * y * z + s * x;  R[8] = c + oc * z * z;
        sJ[t * 3 + 0] = joints[t * 3 + 0];
        sJ[t * 3 + 1] = joints[t * 3 + 1];
        sJ[t * 3 + 2] = joints[t * 3 + 2];
    }
    if (t < NB * 3) {
        int b = t / 3, cc = t % 3;
        g_base[b * 4 + cc] = disp[cc] + est[t];
    }
    if (t < NB) g_base[t * 4 + 3] = 0.0f;
    __syncthreads();

    if (t == 0) {
        float sc = scale[0];
        for (int i = 0; i < NJ; i++) {
            int p = c_parents[i];
            float jx = sJ[i * 3], jy = sJ[i * 3 + 1], jz = sJ[i * 3 + 2];
            float tx = jx, ty = jy, tz = jz;
            if (p >= 0) {
                tx -= sJ[p * 3]; ty -= sJ[p * 3 + 1]; tz -= sJ[p * 3 + 2];
            }
            const float* R = sR + i * 9;
            float* Gi = sG + i * 12;
            if (p < 0) {
                Gi[0] = R[0]; Gi[1] = R[1]; Gi[2]  = R[2]; Gi[3]  = tx;
                Gi[4] = R[3]; Gi[5] = R[4]; Gi[6]  = R[5]; Gi[7]  = ty;
                Gi[8] = R[6]; Gi[9] = R[7]; Gi[10] = R[8]; Gi[11] = tz;
            } else {
                const float* Gp = sG + p * 12;
                #pragma unroll
                for (int r = 0; r < 3; r++) {
                    float m0 = Gp[r * 4 + 0], m1 = Gp[r * 4 + 1],
                          m2 = Gp[r * 4 + 2], mt = Gp[r * 4 + 3];
                    Gi[r * 4 + 0] = m0 * R[0] + m1 * R[3] + m2 * R[6];
                    Gi[r * 4 + 1] = m0 * R[1] + m1 * R[4] + m2 * R[7];
                    Gi[r * 4 + 2] = m0 * R[2] + m1 * R[5] + m2 * R[8];
                    Gi[r * 4 + 3] = m0 * tx + m1 * ty + m2 * tz + mt;
                }
            }
        }
        // A = G with rest translation removed; fold scale in.
        for (int i = 0; i < NJ; i++) {
            float jx = sJ[i * 3], jy = sJ[i * 3 + 1], jz = sJ[i * 3 + 2];
            const float* Gi = sG + i * 12;
            #pragma unroll
            for (int r = 0; r < 3; r++) {
                float tr = Gi[r * 4 + 0] * jx + Gi[r * 4 + 1] * jy + Gi[r * 4 + 2] * jz;
                g_A[i * 12 + r * 4 + 0] = sc * Gi[r * 4 + 0];
                g_A[i * 12 + r * 4 + 1] = sc * Gi[r * 4 + 1];
                g_A[i * 12 + r * 4 + 2] = sc * Gi[r * 4 + 2];
                g_A[i * 12 + r * 4 + 3] = sc * (Gi[r * 4 + 3] - tr);
            }
        }
    }
}

// ---------------------------------------------------------------------------
// Kernel 2: per-vertex skinning + batched broadcast write.
// 4 vertices per thread -> contiguous 48B output chunk per thread per plane,
// all stores are STG.128.
// ---------------------------------------------------------------------------
__global__ __launch_bounds__(256) void lbs_kernel(
    const float* __restrict__ weights,
    const float* __restrict__ v_template,
    const float* __restrict__ local_adjust,
    float* __restrict__ out)
{
    __shared__ float sA[NJ * 12];
    __shared__ float sBase[NB * 4];
    int t = threadIdx.x;
    #pragma unroll
    for (int i = t; i < NJ * 12; i += 256) sA[i] = g_A[i];
    if (t < NB * 4) sBase[t] = g_base[t];
    __syncthreads();

    int v0 = (blockIdx.x * 256 + t) * 4;
    if (v0 >= NV) return;

    // Accumulate T[r] = sum_j w[v0+r][j] * A[j]   (3x4 each)
    float T[4][12];
    #pragma unroll
    for (int r = 0; r < 4; r++)
        #pragma unroll
        for (int k = 0; k < 12; k++) T[r][k] = 0.0f;

    const float* w0 = weights + (size_t)v0 * NJ;
    #pragma unroll
    for (int j = 0; j < NJ; j++) {
        float a[12];
        *(float4*)(a + 0) = *(const float4*)(sA + j * 12 + 0);
        *(float4*)(a + 4) = *(const float4*)(sA + j * 12 + 4);
        *(float4*)(a + 8) = *(const float4*)(sA + j * 12 + 8);
        #pragma unroll
        for (int r = 0; r < 4; r++) {
            float w = __ldg(w0 + r * NJ + j);
            #pragma unroll
            for (int k = 0; k < 12; k++) T[r][k] += w * a[k];
        }
    }

    // v = v_template + local_adjust (12 contiguous floats, 16B aligned)
    float vv[12];
    const float4* vt = (const float4*)(v_template + (size_t)v0 * 3);
    const float4* la = (const float4*)(local_adjust + (size_t)v0 * 3);
    #pragma unroll
    for (int i = 0; i < 3; i++) {
        float4 a4 = __ldg(vt + i);
        float4 b4 = __ldg(la + i);
        vv[i * 4 + 0] = a4.x + b4.x;
        vv[i * 4 + 1] = a4.y + b4.y;
        vv[i * 4 + 2] = a4.z + b4.z;
        vv[i * 4 + 3] = a4.w + b4.w;
    }

    // v_posed[r] = T[r](3x3) * v[r] + T[r].t   (scale already folded into A)
    float vp[4][3];
    #pragma unroll
    for (int r = 0; r < 4; r++) {
        float vx = vv[r * 3 + 0], vy = vv[r * 3 + 1], vz = vv[r * 3 + 2];
        #pragma unroll
        for (int c = 0; c < 3; c++) {
            vp[r][c] = T[r][c * 4 + 0] * vx + T[r][c * 4 + 1] * vy
                     + T[r][c * 4 + 2] * vz + T[r][c * 4 + 3];
        }
    }

    // Broadcast over batch: out[b, v0..v0+3, :] = vp + base[b]
    float* obase = out + (size_t)v0 * 3;
    #pragma unroll
    for (int b = 0; b < NB; b++) {
        float4 bb = *(const float4*)(sBase + b * 4);
        float4 o0, o1, o2;
        o0.x = vp[0][0] + bb.x; o0.y = vp[0][1] + bb.y;
        o0.z = vp[0][2] + bb.z; o0.w = vp[1][0] + bb.x;
        o1.x = vp[1][1] + bb.y; o1.y = vp[1][2] + bb.z;
        o1.z = vp[2][0] + bb.x; o1.w = vp[2][1] + bb.y;
        o2.x = vp[2][2] + bb.z; o2.y = vp[3][0] + bb.x;
        o2.z = vp[3][1] + bb.y; o2.w = vp[3][2] + bb.z;
        float4* op = (float4*)(obase + (size_t)b * (size_t)NV * 3);
        op[0] = o0; op[1] = o1; op[2] = o2;
    }
}

// ---------------------------------------------------------------------------
extern "C" void kernel_launch(void* const* d_in, const int* in_sizes, int n_in,
                              void* d_out, int out_size)
{
    const float* pose         = (const float*)d_in[0]; // (34,3)
    const float* joints       = (const float*)d_in[1]; // (34,3)
    const float* weights      = (const float*)d_in[2]; // (V,34)
    const float* v_template   = (const float*)d_in[3]; // (V,3)
    const float* local_adjust = (const float*)d_in[4]; // (V,3)
    const float* displacement = (const float*)d_in[5]; // (1,3)
    const float* scale        = (const float*)d_in[6]; // (1,)
    const float* est          = (const float*)d_in[7]; // (B,3)
    float* out = (float*)d_out;
    (void)in_sizes; (void)n_in; (void)out_size;

    prep_kernel<<<1, 128>>>(pose, joints, displacement, scale, est);

    int threads_needed = NV / 4;                 // 125000
    int blocks = (threads_needed + 255) / 256;   // 489
    lbs_kernel<<<blocks, 256>>>(weights, v_template, local_adjust, out);
}

// round 3
// speedup vs baseline: 1.6564x; 1.6564x over previous
#include <cuda_runtime.h>
#include <math.h>

#define NJ 34
#define NV 500000
#define NB 32
#define NQ (NV / 4)           // 125000 vertex-quads
#define NQF (NV * 3 / 4)      // 375000 output float4s per batch plane

__constant__ int c_parents[NJ] = {
    -1, 0, 1, 2, 2, 4, 5, 6, 7, 8, 9, 7, 11, 12, 7, 14, 15, 2,
    17, 18, 19, 20, 21, 22, 20, 24, 25, 20, 27, 28, 0, 30, 0, 32
};

// Scratch (device globals; no allocation allowed)
__device__ float g_A[NJ * 12];        // scaled 3x4 affines
__device__ float g_base[NB * 4];      // disp + estimated_location per batch
__device__ float g_vp[NV * 3];        // posed vertices (6 MB)

// ---------------------------------------------------------------------------
// Kernel 1: rodrigues + FK (parallel ancestor-chain products) + folding.
// ---------------------------------------------------------------------------
__global__ void prep_kernel(const float* __restrict__ pose,
                            const float* __restrict__ joints,
                            const float* __restrict__ disp,
                            const float* __restrict__ scale,
                            const float* __restrict__ est)
{
    __shared__ float sT[NJ * 12];   // local 3x4 transforms
    __shared__ float sJ[NJ * 3];
    int t = threadIdx.x;

    if (t < NJ * 3) sJ[t] = joints[t];
    if (t < NB * 3) {
        int b = t / 3, cc = t % 3;
        g_base[b * 4 + cc] = disp[cc] + est[t];
    }
    if (t < NB) g_base[t * 4 + 3] = 0.0f;
    __syncthreads();

    if (t < NJ) {
        float rx = pose[t * 3 + 0], ry = pose[t * 3 + 1], rz = pose[t * 3 + 2];
        float ang = sqrtf(rx * rx + ry * ry + rz * rz + 1e-8f);
        float inv = 1.0f / ang;
        float x = rx * inv, y = ry * inv, z = rz * inv;
        float s = sinf(ang), c = cosf(ang), oc = 1.0f - c;
        int p = c_parents[t];
        float tx = sJ[t * 3 + 0], ty = sJ[t * 3 + 1], tz = sJ[t * 3 + 2];
        if (p >= 0) { tx -= sJ[p * 3 + 0]; ty -= sJ[p * 3 + 1]; tz -= sJ[p * 3 + 2]; }
        float* T = sT + t * 12;
        T[0] = c + oc * x * x;      T[1] = oc * x * y - s * z;  T[2]  = oc * x * z + s * y;  T[3]  = tx;
        T[4] = oc * x * y + s * z;  T[5] = c + oc * y * y;      T[6]  = oc * y * z - s * x;  T[7]  = ty;
        T[8] = oc * x * z - s * y;  T[9] = oc * y * z + s * x;  T[10] = c + oc * z * z;      T[11] = tz;
    }
    __syncthreads();

    if (t < NJ) {
        // ancestor chain: chain[0]=t ... chain[d-1]=root
        int chain[16];
        int d = 0;
        for (int n = t; n >= 0; n = c_parents[n]) chain[d++] = n;
        float G[12];
        const float* Tr = sT + chain[d - 1] * 12;
        #pragma unroll
        for (int k = 0; k < 12; k++) G[k] = Tr[k];
        for (int k = d - 2; k >= 0; k--) {
            const float* Tc = sT + chain[k] * 12;
            float C[12];
            #pragma unroll
            for (int r = 0; r < 3; r++) {
                float g0 = G[r * 4 + 0], g1 = G[r * 4 + 1], g2 = G[r * 4 + 2], g3 = G[r * 4 + 3];
                C[r * 4 + 0] = g0 * Tc[0] + g1 * Tc[4] + g2 * Tc[8];
                C[r * 4 + 1] = g0 * Tc[1] + g1 * Tc[5] + g2 * Tc[9];
                C[r * 4 + 2] = g0 * Tc[2] + g1 * Tc[6] + g2 * Tc[10];
                C[r * 4 + 3] = g0 * Tc[3] + g1 * Tc[7] + g2 * Tc[11] + g3;
            }
            #pragma unroll
            for (int k2 = 0; k2 < 12; k2++) G[k2] = C[k2];
        }
        // remove rest translation, fold scale
        float sc = scale[0];
        float jx = sJ[t * 3 + 0], jy = sJ[t * 3 + 1], jz = sJ[t * 3 + 2];
        #pragma unroll
        for (int r = 0; r < 3; r++) {
            float tr = G[r * 4 + 0] * jx + G[r * 4 + 1] * jy + G[r * 4 + 2] * jz;
            g_A[t * 12 + r * 4 + 0] = sc * G[r * 4 + 0];
            g_A[t * 12 + r * 4 + 1] = sc * G[r * 4 + 1];
            g_A[t * 12 + r * 4 + 2] = sc * G[r * 4 + 2];
            g_A[t * 12 + r * 4 + 3] = sc * (G[r * 4 + 3] - tr);
        }
    }
}

// ---------------------------------------------------------------------------
// Kernel 2: skinning -> v_posed (6 MB scratch). Weights read as float4.
// ---------------------------------------------------------------------------
__global__ __launch_bounds__(256) void skin_kernel(
    const float* __restrict__ weights,
    const float* __restrict__ v_template,
    const float* __restrict__ local_adjust)
{
    __shared__ float sA[NJ * 12];
    int t = threadIdx.x;
    for (int i = t; i < NJ * 12; i += 256) sA[i] = g_A[i];
    __syncthreads();

    int quad = blockIdx.x * 256 + t;
    if (quad >= NQ) return;

    float T[4][12];
    #pragma unroll
    for (int r = 0; r < 4; r++)
        #pragma unroll
        for (int k = 0; k < 12; k++) T[r][k] = 0.0f;

    // 544-byte contiguous weight block per quad = 34 float4 loads
    const float4* wq = (const float4*)weights + (size_t)quad * 34;
    #pragma unroll
    for (int k = 0; k < 34; k++) {
        float4 w4 = wq[k];
        float wv[4] = {w4.x, w4.y, w4.z, w4.w};
        #pragma unroll
        for (int e = 0; e < 4; e++) {
            const int idx = 4 * k + e;       // compile-time
            const int r = idx / 34;
            const int j = idx % 34;
            const float* Aj = sA + j * 12;
            float w = wv[e];
            #pragma unroll
            for (int q = 0; q < 12; q++) T[r][q] += w * Aj[q];
        }
    }

    // v = v_template + local_adjust (12 contiguous floats per quad)
    float vv[12];
    const float4* vt = (const float4*)(v_template + (size_t)quad * 12);
    const float4* la = (const float4*)(local_adjust + (size_t)quad * 12);
    #pragma unroll
    for (int i = 0; i < 3; i++) {
        float4 a4 = vt[i];
        float4 b4 = la[i];
        vv[i * 4 + 0] = a4.x + b4.x;
        vv[i * 4 + 1] = a4.y + b4.y;
        vv[i * 4 + 2] = a4.z + b4.z;
        vv[i * 4 + 3] = a4.w + b4.w;
    }

    float vp[4][3];
    #pragma unroll
    for (int r = 0; r < 4; r++) {
        float vx = vv[r * 3 + 0], vy = vv[r * 3 + 1], vz = vv[r * 3 + 2];
        #pragma unroll
        for (int c = 0; c < 3; c++) {
            vp[r][c] = T[r][c * 4 + 0] * vx + T[r][c * 4 + 1] * vy
                     + T[r][c * 4 + 2] * vz + T[r][c * 4 + 3];
        }
    }

    float4 o0, o1, o2;
    o0.x = vp[0][0]; o0.y = vp[0][1]; o0.z = vp[0][2]; o0.w = vp[1][0];
    o1.x = vp[1][1]; o1.y = vp[1][2]; o1.z = vp[2][0]; o1.w = vp[2][1];
    o2.x = vp[2][2]; o2.y = vp[3][0]; o2.z = vp[3][1]; o2.w = vp[3][2];
    float4* op = (float4*)g_vp + (size_t)quad * 3;
    op[0] = o0; op[1] = o1; op[2] = o2;
}

// ---------------------------------------------------------------------------
// Kernel 3: broadcast over batch. grid.y = batch plane -> no per-thread
// divide. One thread per output float4; coalesced read (L2-hot) + write.
// ---------------------------------------------------------------------------
__global__ __launch_bounds__(256) void bcast_kernel(float4* __restrict__ out)
{
    int r = blockIdx.x * 256 + threadIdx.x;       // float4 index within plane
    if (r >= NQF) return;
    int b = blockIdx.y;

    float4 v = __ldg((const float4*)g_vp + r);
    float b0 = g_base[b * 4 + 0];
    float b1 = g_base[b * 4 + 1];
    float b2 = g_base[b * 4 + 2];

    int m = r % 3;   // component phase of first float in this float4
    float s0 = (m == 0) ? b0 : ((m == 1) ? b1 : b2);
    float s1 = (m == 0) ? b1 : ((m == 1) ? b2 : b0);
    float s2 = (m == 0) ? b2 : ((m == 1) ? b0 : b1);

    v.x += s0; v.y += s1; v.z += s2; v.w += s0;
    out[(size_t)b * NQF + r] = v;
}

// ---------------------------------------------------------------------------
extern "C" void kernel_launch(void* const* d_in, const int* in_sizes, int n_in,
                              void* d_out, int out_size)
{
    const float* pose         = (const float*)d_in[0]; // (34,3)
    const float* joints       = (const float*)d_in[1]; // (34,3)
    const float* weights      = (const float*)d_in[2]; // (V,34)
    const float* v_template   = (const float*)d_in[3]; // (V,3)
    const float* local_adjust = (const float*)d_in[4]; // (V,3)
    const float* displacement = (const float*)d_in[5]; // (1,3)
    const float* scale        = (const float*)d_in[6]; // (1,)
    const float* est          = (const float*)d_in[7]; // (B,3)
    float* out = (float*)d_out;
    (void)in_sizes; (void)n_in; (void)out_size;

    prep_kernel<<<1, 128>>>(pose, joints, displacement, scale, est);

    int blocksA = (NQ + 255) / 256;               // 489
    skin_kernel<<<blocksA, 256>>>(weights, v_template, local_adjust);

    dim3 gridB((NQF + 255) / 256, NB);            // 1465 x 32
    bcast_kernel<<<gridB, 256>>>((float4*)out);
}

// round 4
// speedup vs baseline: 1.7979x; 1.0854x over previous
#include <cuda_runtime.h>
#include <math.h>

#define NJ 34
#define NV 500000
#define NB 32
#define NQ (NV / 4)            // 125000 vertex-quads
#define NQF (NV * 3 / 4)       // 375000 output float4s per batch plane
#define BLK 256
#define F4_PER_BLK (BLK * 3)   // 768 float4s of output per plane per block

__constant__ int c_parents[NJ] = {
    -1, 0, 1, 2, 2, 4, 5, 6, 7, 8, 9, 7, 11, 12, 7, 14, 15, 2,
    17, 18, 19, 20, 21, 22, 20, 24, 25, 20, 27, 28, 0, 30, 0, 32
};

// ---------------------------------------------------------------------------
// Single fused kernel:
//   phase 0: block-local A (rodrigues + FK chain + scale fold) and base table
//   phase 1: skin 256 quads (4 verts/thread), float4 weight loads
//   phase 2: stage 12KB posed verts in shared, write 32 planes coalesced
// ---------------------------------------------------------------------------
__global__ __launch_bounds__(BLK) void fused_lbs_kernel(
    const float* __restrict__ pose,
    const float* __restrict__ joints,
    const float* __restrict__ weights,
    const float* __restrict__ v_template,
    const float* __restrict__ local_adjust,
    const float* __restrict__ disp,
    const float* __restrict__ scale,
    const float* __restrict__ est,
    float4* __restrict__ out)
{
    __shared__ float sA[NJ * 12];                 // scaled 3x4 affines
    __shared__ float sBase[NB * 4];               // disp + est per batch
    __shared__ __align__(16) float sVP[BLK * 12]; // staging (aliased for sT/sJ)

    // Alias scratch for phase 0 inside the staging buffer (dead until phase 2)
    float* sT = sVP;            // NJ*12 = 408 floats
    float* sJ = sVP + 512;      // NJ*3  = 102 floats

    int t = threadIdx.x;

    // ---- phase 0a: base table + joints into shared ----
    if (t < NB * 3) {
        int b = t / 3, cc = t - b * 3;
        sBase[b * 4 + cc] = disp[cc] + est[t];
    } else if (t >= 96 && t < 96 + NB) {
        sBase[(t - 96) * 4 + 3] = 0.0f;
    }
    if (t < NJ * 3) sJ[t] = joints[t];
    __syncthreads();

    // ---- phase 0b: local transforms ----
    if (t < NJ) {
        float rx = pose[t * 3 + 0], ry = pose[t * 3 + 1], rz = pose[t * 3 + 2];
        float ang = sqrtf(rx * rx + ry * ry + rz * rz + 1e-8f);
        float inv = 1.0f / ang;
        float x = rx * inv, y = ry * inv, z = rz * inv;
        float s = sinf(ang), c = cosf(ang), oc = 1.0f - c;
        int p = c_parents[t];
        float tx = sJ[t * 3 + 0], ty = sJ[t * 3 + 1], tz = sJ[t * 3 + 2];
        if (p >= 0) { tx -= sJ[p * 3 + 0]; ty -= sJ[p * 3 + 1]; tz -= sJ[p * 3 + 2]; }
        float* T = sT + t * 12;
        T[0] = c + oc * x * x;      T[1] = oc * x * y - s * z;  T[2]  = oc * x * z + s * y;  T[3]  = tx;
        T[4] = oc * x * y + s * z;  T[5] = c + oc * y * y;      T[6]  = oc * y * z - s * x;  T[7]  = ty;
        T[8] = oc * x * z - s * y;  T[9] = oc * y * z + s * x;  T[10] = c + oc * z * z;      T[11] = tz;
    }
    __syncthreads();

    // ---- phase 0c: ancestor-chain composition -> A (scale folded) ----
    if (t < NJ) {
        int chain[16];
        int d = 0;
        for (int n = t; n >= 0; n = c_parents[n]) chain[d++] = n;
        float G[12];
        const float* Tr = sT + chain[d - 1] * 12;
        #pragma unroll
        for (int k = 0; k < 12; k++) G[k] = Tr[k];
        for (int k = d - 2; k >= 0; k--) {
            const float* Tc = sT + chain[k] * 12;
            float C[12];
            #pragma unroll
            for (int r = 0; r < 3; r++) {
                float g0 = G[r * 4 + 0], g1 = G[r * 4 + 1], g2 = G[r * 4 + 2], g3 = G[r * 4 + 3];
                C[r * 4 + 0] = g0 * Tc[0] + g1 * Tc[4] + g2 * Tc[8];
                C[r * 4 + 1] = g0 * Tc[1] + g1 * Tc[5] + g2 * Tc[9];
                C[r * 4 + 2] = g0 * Tc[2] + g1 * Tc[6] + g2 * Tc[10];
                C[r * 4 + 3] = g0 * Tc[3] + g1 * Tc[7] + g2 * Tc[11] + g3;
            }
            #pragma unroll
            for (int k2 = 0; k2 < 12; k2++) G[k2] = C[k2];
        }
        float sc = scale[0];
        float jx = sJ[t * 3 + 0], jy = sJ[t * 3 + 1], jz = sJ[t * 3 + 2];
        #pragma unroll
        for (int r = 0; r < 3; r++) {
            float tr = G[r * 4 + 0] * jx + G[r * 4 + 1] * jy + G[r * 4 + 2] * jz;
            sA[t * 12 + r * 4 + 0] = sc * G[r * 4 + 0];
            sA[t * 12 + r * 4 + 1] = sc * G[r * 4 + 1];
            sA[t * 12 + r * 4 + 2] = sc * G[r * 4 + 2];
            sA[t * 12 + r * 4 + 3] = sc * (G[r * 4 + 3] - tr);
        }
    }
    __syncthreads();   // sT/sJ dead from here; sVP free for staging

    // ---- phase 1: skin 4 vertices ----
    int quad = blockIdx.x * BLK + t;
    float vp[4][3];

    if (quad < NQ) {
        float T[4][12];
        #pragma unroll
        for (int r = 0; r < 4; r++)
            #pragma unroll
            for (int k = 0; k < 12; k++) T[r][k] = 0.0f;

        const float4* wq = (const float4*)weights + (size_t)quad * 34;
        #pragma unroll
        for (int k = 0; k < 34; k++) {
            float4 w4 = __ldcs(wq + k);
            float wv[4] = {w4.x, w4.y, w4.z, w4.w};
            #pragma unroll
            for (int e = 0; e < 4; e++) {
                const int idx = 4 * k + e;      // compile-time
                const int r = idx / 34;
                const int j = idx % 34;
                const float* Aj = sA + j * 12;
                float w = wv[e];
                #pragma unroll
                for (int q = 0; q < 12; q++) T[r][q] += w * Aj[q];
            }
        }

        float vv[12];
        const float4* vt = (const float4*)(v_template + (size_t)quad * 12);
        const float4* la = (const float4*)(local_adjust + (size_t)quad * 12);
        #pragma unroll
        for (int i = 0; i < 3; i++) {
            float4 a4 = __ldcs(vt + i);
            float4 b4 = __ldcs(la + i);
            vv[i * 4 + 0] = a4.x + b4.x;
            vv[i * 4 + 1] = a4.y + b4.y;
            vv[i * 4 + 2] = a4.z + b4.z;
            vv[i * 4 + 3] = a4.w + b4.w;
        }

        #pragma unroll
        for (int r = 0; r < 4; r++) {
            float vx = vv[r * 3 + 0], vy = vv[r * 3 + 1], vz = vv[r * 3 + 2];
            #pragma unroll
            for (int c = 0; c < 3; c++) {
                vp[r][c] = T[r][c * 4 + 0] * vx + T[r][c * 4 + 1] * vy
                         + T[r][c * 4 + 2] * vz + T[r][c * 4 + 3];
            }
        }
    } else {
        #pragma unroll
        for (int r = 0; r < 4; r++)
            #pragma unroll
            for (int c = 0; c < 3; c++) vp[r][c] = 0.0f;
    }

    // ---- phase 2: stage to shared, then write all planes coalesced ----
    __syncthreads();   // everyone past phase-0 reads of sVP alias
    {
        float* dst = sVP + t * 12;
        float4 p0, p1, p2;
        p0.x = vp[0][0]; p0.y = vp[0][1]; p0.z = vp[0][2]; p0.w = vp[1][0];
        p1.x = vp[1][1]; p1.y = vp[1][2]; p1.z = vp[2][0]; p1.w = vp[2][1];
        p2.x = vp[2][2]; p2.y = vp[3][0]; p2.z = vp[3][1]; p2.w = vp[3][2];
        ((float4*)dst)[0] = p0; ((float4*)dst)[1] = p1; ((float4*)dst)[2] = p2;
    }
    __syncthreads();

    int block_f4 = blockIdx.x * F4_PER_BLK;        // multiple of 3
    int valid = NQF - block_f4;
    if (valid > F4_PER_BLK) valid = F4_PER_BLK;

    #pragma unroll
    for (int i = 0; i < 3; i++) {
        int idx = i * BLK + t;
        if (idx < valid) {
            float4 v = ((const float4*)sVP)[idx];
            int m = idx % 3;                       // block_f4 % 3 == 0
            #pragma unroll
            for (int b = 0; b < NB; b++) {
                float b0 = sBase[b * 4 + 0];
                float b1 = sBase[b * 4 + 1];
                float b2 = sBase[b * 4 + 2];
                float s0 = (m == 0) ? b0 : ((m == 1) ? b1 : b2);
                float s1 = (m == 0) ? b1 : ((m == 1) ? b2 : b0);
                float s2 = (m == 0) ? b2 : ((m == 1) ? b0 : b1);
                float4 o;
                o.x = v.x + s0; o.y = v.y + s1; o.z = v.z + s2; o.w = v.w + s0;
                __stcs(out + (size_t)b * NQF + block_f4 + idx, o);
            }
        }
    }
}

// ---------------------------------------------------------------------------
extern "C" void kernel_launch(void* const* d_in, const int* in_sizes, int n_in,
                              void* d_out, int out_size)
{
    const float* pose         = (const float*)d_in[0]; // (34,3)
    const float* joints       = (const float*)d_in[1]; // (34,3)
    const float* weights      = (const float*)d_in[2]; // (V,34)
    const float* v_template   = (const float*)d_in[3]; // (V,3)
    const float* local_adjust = (const float*)d_in[4]; // (V,3)
    const float* displacement = (const float*)d_in[5]; // (1,3)
    const float* scale        = (const float*)d_in[6]; // (1,)
    const float* est          = (const float*)d_in[7]; // (B,3)
    float* out = (float*)d_out;
    (void)in_sizes; (void)n_in; (void)out_size;

    int blocks = (NQ + BLK - 1) / BLK;             // 489
    fused_lbs_kernel<<<blocks, BLK>>>(pose, joints, weights, v_template,
                                      local_adjust, displacement, scale, est,
                                      (float4*)out);
}

// round 5
// speedup vs baseline: 2.0364x; 1.1327x over previous
#include <cuda_runtime.h>
#include <math.h>

#define NJ 34
#define NV 500000
#define NB 32
#define NQF (NV * 3 / 4)       // 375000 output float4s per batch plane
#define BLK 256
#define NBLOCKS ((NV + BLK - 1) / BLK)   // 1954
#define F4_PER_BLK (BLK * 3 / 4)         // 192 float4s per plane per block
#define W_STRIDE 1088                     // floats of weights per warp (32*34)

__constant__ int c_parents[NJ] = {
    -1, 0, 1, 2, 2, 4, 5, 6, 7, 8, 9, 7, 11, 12, 7, 14, 15, 2,
    17, 18, 19, 20, 21, 22, 20, 24, 25, 20, 27, 28, 0, 30, 0, 32
};

// ---------------------------------------------------------------------------
// One fused kernel, 1 vertex/thread:
//   phase 0: block-local A (rodrigues + FK + scale fold) and base table
//   phase 1: warp-cooperative coalesced weight staging -> LDS -> skin
//   phase 2: stage posed verts in shared, write 32 planes as float4 (stcs)
// ---------------------------------------------------------------------------
__global__ __launch_bounds__(BLK) void fused_lbs_kernel(
    const float* __restrict__ pose,
    const float* __restrict__ joints,
    const float* __restrict__ weights,
    const float* __restrict__ v_template,
    const float* __restrict__ local_adjust,
    const float* __restrict__ disp,
    const float* __restrict__ scale,
    const float* __restrict__ est,
    float4* __restrict__ out)
{
    __shared__ float sA[NJ * 12];
    __shared__ float sBase[NB * 4];
    __shared__ __align__(16) float sW[8 * W_STRIDE];   // 34 KB weight staging
    __shared__ __align__(16) float sVP[BLK * 3];       // 3 KB posed verts

    // phase-0 scratch aliased inside sW (dead until phase 1)
    float* sT = sW;           // NJ*12 = 408 floats
    float* sJ = sW + 512;     // NJ*3

    const int t = threadIdx.x;
    const int w = t >> 5;
    const int l = t & 31;

    // ---- phase 0a: base table + joints ----
    if (t < NB * 3) {
        int b = t / 3, cc = t - b * 3;
        sBase[b * 4 + cc] = disp[cc] + est[t];
    } else if (t >= 96 && t < 96 + NB) {
        sBase[(t - 96) * 4 + 3] = 0.0f;
    }
    if (t < NJ * 3) sJ[t] = joints[t];
    __syncthreads();

    // ---- phase 0b: local transforms ----
    if (t < NJ) {
        float rx = pose[t * 3 + 0], ry = pose[t * 3 + 1], rz = pose[t * 3 + 2];
        float ang = sqrtf(rx * rx + ry * ry + rz * rz + 1e-8f);
        float inv = 1.0f / ang;
        float x = rx * inv, y = ry * inv, z = rz * inv;
        float s = sinf(ang), c = cosf(ang), oc = 1.0f - c;
        int p = c_parents[t];
        float tx = sJ[t * 3 + 0], ty = sJ[t * 3 + 1], tz = sJ[t * 3 + 2];
        if (p >= 0) { tx -= sJ[p * 3 + 0]; ty -= sJ[p * 3 + 1]; tz -= sJ[p * 3 + 2]; }
        float* T = sT + t * 12;
        T[0] = c + oc * x * x;      T[1] = oc * x * y - s * z;  T[2]  = oc * x * z + s * y;  T[3]  = tx;
        T[4] = oc * x * y + s * z;  T[5] = c + oc * y * y;      T[6]  = oc * y * z - s * x;  T[7]  = ty;
        T[8] = oc * x * z - s * y;  T[9] = oc * y * z + s * x;  T[10] = c + oc * z * z;      T[11] = tz;
    }
    __syncthreads();

    // ---- phase 0c: ancestor-chain composition -> A (scale folded) ----
    if (t < NJ) {
        int chain[16];
        int d = 0;
        for (int n = t; n >= 0; n = c_parents[n]) chain[d++] = n;
        float G[12];
        const float* Tr = sT + chain[d - 1] * 12;
        #pragma unroll
        for (int k = 0; k < 12; k++) G[k] = Tr[k];
        for (int k = d - 2; k >= 0; k--) {
            const float* Tc = sT + chain[k] * 12;
            float C[12];
            #pragma unroll
            for (int r = 0; r < 3; r++) {
                float g0 = G[r * 4 + 0], g1 = G[r * 4 + 1], g2 = G[r * 4 + 2], g3 = G[r * 4 + 3];
                C[r * 4 + 0] = g0 * Tc[0] + g1 * Tc[4] + g2 * Tc[8];
                C[r * 4 + 1] = g0 * Tc[1] + g1 * Tc[5] + g2 * Tc[9];
                C[r * 4 + 2] = g0 * Tc[2] + g1 * Tc[6] + g2 * Tc[10];
                C[r * 4 + 3] = g0 * Tc[3] + g1 * Tc[7] + g2 * Tc[11] + g3;
            }
            #pragma unroll
            for (int k2 = 0; k2 < 12; k2++) G[k2] = C[k2];
        }
        float sc = scale[0];
        float jx = sJ[t * 3 + 0], jy = sJ[t * 3 + 1], jz = sJ[t * 3 + 2];
        #pragma unroll
        for (int r = 0; r < 3; r++) {
            float tr = G[r * 4 + 0] * jx + G[r * 4 + 1] * jy + G[r * 4 + 2] * jz;
            sA[t * 12 + r * 4 + 0] = sc * G[r * 4 + 0];
            sA[t * 12 + r * 4 + 1] = sc * G[r * 4 + 1];
            sA[t * 12 + r * 4 + 2] = sc * G[r * 4 + 2];
            sA[t * 12 + r * 4 + 3] = sc * (G[r * 4 + 3] - tr);
        }
    }
    __syncthreads();   // sT/sJ dead; sW free for weight staging

    // ---- phase 1a: warp-cooperative coalesced weight staging ----
    const int block_base = blockIdx.x * BLK;
    const int warp_base = block_base + w * 32;
    const int v = block_base + t;               // this thread's vertex

    if (warp_base < NV) {
        // 32 verts * 34 floats = 1088 floats = 272 float4, contiguous, 16B-aligned
        const size_t f4_base = (size_t)warp_base * 34 / 4;
        const size_t f4_total = (size_t)NV * 34 / 4;
        const float4* srcw = (const float4*)weights;
        float4* dstw = (float4*)(sW + w * W_STRIDE);
        #pragma unroll
        for (int i = 0; i < 9; i++) {
            int idx = i * 32 + l;
            if (idx < 272 && f4_base + idx < f4_total)
                dstw[idx] = __ldcs(srcw + f4_base + idx);
        }
    }
    __syncwarp();

    // ---- phase 1b: skin ----
    float vp0 = 0.0f, vp1 = 0.0f, vp2 = 0.0f;
    if (v < NV) {
        float T[12];
        #pragma unroll
        for (int k = 0; k < 12; k++) T[k] = 0.0f;

        const float2* wp = (const float2*)(sW + w * W_STRIDE + l * 34);
        #pragma unroll
        for (int k = 0; k < 17; k++) {
            float2 w2 = wp[k];
            {
                const float* Aj = sA + (2 * k) * 12;
                float a[12];
                *(float4*)(a + 0) = *(const float4*)(Aj + 0);
                *(float4*)(a + 4) = *(const float4*)(Aj + 4);
                *(float4*)(a + 8) = *(const float4*)(Aj + 8);
                #pragma unroll
                for (int q = 0; q < 12; q++) T[q] += w2.x * a[q];
            }
            {
                const float* Aj = sA + (2 * k + 1) * 12;
                float a[12];
                *(float4*)(a + 0) = *(const float4*)(Aj + 0);
                *(float4*)(a + 4) = *(const float4*)(Aj + 4);
                *(float4*)(a + 8) = *(const float4*)(Aj + 8);
                #pragma unroll
                for (int q = 0; q < 12; q++) T[q] += w2.y * a[q];
            }
        }

        const float* vtp = v_template + (size_t)v * 3;
        const float* lap = local_adjust + (size_t)v * 3;
        float vx = __ldcs(vtp + 0) + __ldcs(lap + 0);
        float vy = __ldcs(vtp + 1) + __ldcs(lap + 1);
        float vz = __ldcs(vtp + 2) + __ldcs(lap + 2);

        vp0 = T[0] * vx + T[1] * vy + T[2]  * vz + T[3];
        vp1 = T[4] * vx + T[5] * vy + T[6]  * vz + T[7];
        vp2 = T[8] * vx + T[9] * vy + T[10] * vz + T[11];
    }

    // ---- phase 2: stage + batched coalesced stores ----
    __syncthreads();                 // weight staging reads done block-wide
    sVP[t * 3 + 0] = vp0;
    sVP[t * 3 + 1] = vp1;
    sVP[t * 3 + 2] = vp2;
    __syncthreads();

    if (t < F4_PER_BLK) {
        int block_f4 = blockIdx.x * F4_PER_BLK;    // multiple of 3
        // exact-float4 validity: NV % BLK leaves whole float4s (remainder 32 verts)
        int valid = (NV * 3 - block_f4 * 4 + 3) / 4 - 0;  // floats remaining /4
        valid = (NV * 3 / 4) - block_f4;                  // = NQF - block_f4
        if (t < valid) {
            float4 pv = ((const float4*)sVP)[t];
            int m = t % 3;
            #pragma unroll
            for (int b = 0; b < NB; b++) {
                float b0 = sBase[b * 4 + 0];
                float b1 = sBase[b * 4 + 1];
                float b2 = sBase[b * 4 + 2];
                float s0 = (m == 0) ? b0 : ((m == 1) ? b1 : b2);
                float s1 = (m == 0) ? b1 : ((m == 1) ? b2 : b0);
                float s2 = (m == 0) ? b2 : ((m == 1) ? b0 : b1);
                float4 o;
                o.x = pv.x + s0; o.y = pv.y + s1; o.z = pv.z + s2; o.w = pv.w + s0;
                __stcs(out + (size_t)b * NQF + block_f4 + t, o);
            }
        }
    }
}

// ---------------------------------------------------------------------------
extern "C" void kernel_launch(void* const* d_in, const int* in_sizes, int n_in,
                              void* d_out, int out_size)
{
    const float* pose         = (const float*)d_in[0]; // (34,3)
    const float* joints       = (const float*)d_in[1]; // (34,3)
    const float* weights      = (const float*)d_in[2]; // (V,34)
    const float* v_template   = (const float*)d_in[3]; // (V,3)
    const float* local_adjust = (const float*)d_in[4]; // (V,3)
    const float* displacement = (const float*)d_in[5]; // (1,3)
    const float* scale        = (const float*)d_in[6]; // (1,)
    const float* est          = (const float*)d_in[7]; // (B,3)
    float* out = (float*)d_out;
    (void)in_sizes; (void)n_in; (void)out_size;

    fused_lbs_kernel<<<NBLOCKS, BLK>>>(pose, joints, weights, v_template,
                                       local_adjust, displacement, scale, est,
                                       (float4*)out);
}